// round 11
// baseline (speedup 1.0000x reference)
#include <cuda_runtime.h>
#include <cuda_fp16.h>
#include <cstdint>

// Problem constants (fixed shapes from setup_inputs)
#define BB   16
#define NN   1536
#define CC   768
#define N0   3072
#define HH   64
#define WW   48
#define HW   (HH*WW)            // 3072
#define FM   (BB*HW*CC)         // 37,748,736 elements
#define NPTS (BB*N0)            // 49,152
#define EPSF 1e-6f
#define XSEG 12                 // conv columns per block (4 segments per row)

// Scratch (device globals: allocation-free, per harness rules)
__device__ __align__(16) __half g_raw [FM];      // normalized token2map map, fp16
__device__ __align__(16) __half g_cv  [FM];      // post-conv map,            fp16
__device__ __align__(16) float  g_rc  [BB*HW];   // 1/(cnt+eps), 0 for empty pixels
__device__ __align__(16) float  g_wsum[BB*NN];   // sum(agg_w) -> 1/(sum+eps)
__device__ __align__(16) float  g_wT  [9*CC];    // conv weights transposed [k][C]
__device__ int g_icnt[BB*HW];                    // per-pixel point count
__device__ int g_tcnt[BB*NN];                    // per-token point count

__device__ __forceinline__ void red_add4(float* p, float4 v) {
    asm volatile("red.global.add.v4.f32 [%0], {%1,%2,%3,%4};"
                 :: "l"(p), "f"(v.x), "f"(v.y), "f"(v.z), "f"(v.w) : "memory");
}
__device__ __forceinline__ void red_addh2(unsigned* p, unsigned v) {
    asm volatile("red.global.add.noftz.f16x2 [%0], %1;"
                 :: "l"(p), "r"(v) : "memory");
}

// pixel coords matching jnp: pos = 0.5*(clip(loc,-1,1)+1)*wh - 0.5, unfused to match rounding
__device__ __forceinline__ float pix_coord(float l, float wh) {
    l = fminf(fmaxf(l, -1.0f), 1.0f);
    float t = __fmul_rn(0.5f, __fadd_rn(l, 1.0f));
    return __fadd_rn(__fmul_rn(t, wh), -0.5f);
}

__device__ __forceinline__ float4 h4_to_f4(uint2 pk) {
    __half2 h0 = *(__half2*)&pk.x;
    __half2 h1 = *(__half2*)&pk.y;
    float2 f0 = __half22float2(h0);
    float2 f1 = __half22float2(h1);
    return make_float4(f0.x, f0.y, f1.x, f1.y);
}
__device__ __forceinline__ uint2 f4_to_h4(float4 v) {
    __half2 h0 = __float22half2_rn(make_float2(v.x, v.y));
    __half2 h1 = __float22half2_rn(make_float2(v.z, v.w));
    uint2 pk;
    pk.x = *(unsigned*)&h0;
    pk.y = *(unsigned*)&h1;
    return pk;
}

// ---------------- zero small metadata ----------------
__global__ void k_zero_meta() {
    int i = blockIdx.x * blockDim.x + threadIdx.x;
    if (i < BB*HW) g_icnt[i] = 0;
    if (i < BB*NN) { g_tcnt[i] = 0; g_wsum[i] = 0.0f; }
}

// ---------------- counts + weight sums ----------------
__global__ void k_count(const float* __restrict__ loc_orig,
                        const int*   __restrict__ idx_agg,
                        const float* __restrict__ agg_w) {
    int p = blockIdx.x * blockDim.x + threadIdx.x;
    if (p >= NPTS) return;
    int b = p / N0;
    float px = pix_coord(loc_orig[2*p],   (float)WW);
    float py = pix_coord(loc_orig[2*p+1], (float)HH);
    int ix = min(max((int)rintf(px), 0), WW-1);   // rintf = round-half-even = jnp.round
    int iy = min(max((int)rintf(py), 0), HH-1);
    atomicAdd(&g_icnt[b*HW + iy*WW + ix], 1);
    int seg = b*NN + idx_agg[p];
    atomicAdd(&g_tcnt[seg], 1);
    atomicAdd(&g_wsum[seg], agg_w[p]);
}

// ---------------- reciprocals + weight transpose ----------------
__global__ void k_prep(const float* __restrict__ conv_w) {
    int i = blockIdx.x * blockDim.x + threadIdx.x;
    if (i < 9*CC) {
        int c = i / 9, k = i % 9;           // conv_w layout [C][1][3][3]
        g_wT[k*CC + c] = conv_w[i];
    } else if (i < 9*CC + BB*HW) {
        int j = i - 9*CC;
        int n = g_icnt[j];
        g_rc[j] = (n > 0) ? 1.0f / ((float)n + EPSF) : 0.0f;
    } else if (i < 9*CC + BB*HW + BB*NN) {
        int j = i - 9*CC - BB*HW;
        g_wsum[j] = 1.0f / (g_wsum[j] + EPSF);
    }
}

// ---------------- zero fp16 raw rows with cnt>=2 (persistent, 4-row unroll) ----------------
__global__ __launch_bounds__(192) void k_zero_raw() {
    const int c4 = threadIdx.x;
    const uint2 z = make_uint2(0u, 0u);
    for (int base = blockIdx.x * 4; base < BB*HW; base += gridDim.x * 4) {
        int need[4];
        #pragma unroll
        for (int j = 0; j < 4; j++)
            need[j] = (base + j < BB*HW) && (__ldg(&g_icnt[base+j]) >= 2);
        #pragma unroll
        for (int j = 0; j < 4; j++)
            if (need[j]) ((uint2*)(g_raw + (size_t)(base+j)*CC))[c4] = z;
    }
}

// ---------------- zero out rows with tcnt!=1 (runs on side stream) ----------------
__global__ __launch_bounds__(192) void k_zero_out(float* __restrict__ out) {
    const int c4 = threadIdx.x;
    const float4 z = make_float4(0.f, 0.f, 0.f, 0.f);
    for (int base = blockIdx.x * 4; base < BB*NN; base += gridDim.x * 4) {
        int need[4];
        #pragma unroll
        for (int j = 0; j < 4; j++)
            need[j] = (base + j < BB*NN) && (__ldg(&g_tcnt[base+j]) != 1);
        #pragma unroll
        for (int j = 0; j < 4; j++)
            if (need[j]) ((float4*)(out + (size_t)(base+j)*CC))[c4] = z;
    }
}

// ---------------- feature scatter, pre-normalized, fp16 map; STG when single ----------------
__global__ __launch_bounds__(192) void k_scatter(const float* __restrict__ x,
                                                 const float* __restrict__ loc_orig,
                                                 const int*   __restrict__ idx_agg) {
    int p = blockIdx.x;
    int b = p / N0;
    float px = pix_coord(loc_orig[2*p],   (float)WW);
    float py = pix_coord(loc_orig[2*p+1], (float)HH);
    int ix = min(max((int)rintf(px), 0), WW-1);
    int iy = min(max((int)rintf(py), 0), HH-1);
    int pix = b*HW + iy*WW + ix;
    int tok = idx_agg[p];
    float rc = __ldg(&g_rc[pix]);            // 1/(cnt+eps)
    int cnt  = __ldg(&g_icnt[pix]);
    const float4* src = (const float4*)(x + ((size_t)b*NN + tok)*CC);
    __half* dst = g_raw + (size_t)pix*CC;
    int c4 = threadIdx.x;                    // 192 threads, C/4 = 192
    float4 v = __ldg(&src[c4]);
    v.x *= rc; v.y *= rc; v.z *= rc; v.w *= rc;
    uint2 pk = f4_to_h4(v);
    if (cnt == 1) {
        ((uint2*)dst)[c4] = pk;
    } else {
        unsigned* pp = (unsigned*)dst + 2*c4;
        red_addh2(pp,     pk.x);
        red_addh2(pp + 1, pk.y);
    }
}

// ---------------- row-sliding depthwise 3x3 conv, fp16 in/out, software-pipelined ----------------
__global__ __launch_bounds__(192) void k_conv(const float* __restrict__ conv_b) {
    __shared__ float s_rc[3][WW];
    const int seg = blockIdx.x;              // column segment (WW/XSEG of them)
    const int by  = blockIdx.y;              // b*HH + y
    const int b   = by / HH;
    const int y   = by - b*HH;
    const int tid = threadIdx.x;
    const int x0  = seg * XSEG;

    // rc masks for rows y-1..y+1 (0 outside image / empty pixel)
    for (int i = tid; i < 3*WW; i += 192) {
        int r = i / WW, xx = i - (i / WW)*WW;
        int gy = y + r - 1;
        s_rc[r][xx] = (gy >= 0 && gy < HH) ? __ldg(&g_rc[b*HW + gy*WW + xx]) : 0.0f;
    }
    __syncthreads();

    const int c4 = tid;
    float4 w[9];
    #pragma unroll
    for (int k = 0; k < 9; k++)
        w[k] = *(const float4*)(g_wT + k*CC + 4*c4);
    const float4 bias = ((const float4*)conv_b)[c4];

    const float4 z = make_float4(0.f, 0.f, 0.f, 0.f);
    const size_t rowbase = (size_t)b*HW + (size_t)(y-1)*WW;

    // masked fp16 column load: row r (0..2), column x
    auto ldc = [&](int r, int x) -> float4 {
        if (x < 0 || x >= WW || s_rc[r][x] == 0.0f) return z;
        uint2 pk = __ldg(((const uint2*)(g_raw + (rowbase + (size_t)r*WW + x)*CC)) + c4);
        return h4_to_f4(pk);
    };

    float4 win[3][3];                        // [row][cpos]: 0 = x-1, 1 = x, 2 = x+1
    float4 nxt[3];
    #pragma unroll
    for (int r = 0; r < 3; r++) {
        win[r][0] = ldc(r, x0 - 1);
        win[r][1] = ldc(r, x0);
        nxt[r]    = ldc(r, x0 + 1);
    }

    for (int xi = 0; xi < XSEG; xi++) {
        int x = x0 + xi;
        #pragma unroll
        for (int r = 0; r < 3; r++) win[r][2] = nxt[r];
        // prefetch column x+2 (consumed next iteration -> latency hidden)
        float4 pf[3];
        #pragma unroll
        for (int r = 0; r < 3; r++) pf[r] = ldc(r, x + 2);
        // compute
        float4 acc = bias;
        #pragma unroll
        for (int r = 0; r < 3; r++) {
            #pragma unroll
            for (int cc = 0; cc < 3; cc++) {
                float4 v = win[r][cc];
                float4 wv = w[r*3 + cc];
                acc.x += v.x * wv.x;
                acc.y += v.y * wv.y;
                acc.z += v.z * wv.z;
                acc.w += v.w * wv.w;
            }
        }
        ((uint2*)(g_cv + ((size_t)b*HW + (size_t)y*WW + x)*CC))[c4] = f4_to_h4(acc);
        // shift window
        #pragma unroll
        for (int r = 0; r < 3; r++) {
            win[r][0] = win[r][1];
            win[r][1] = win[r][2];
            nxt[r]    = pf[r];
        }
    }
}

// ---------------- bilinear gather (fp16 map) + token aggregation; STG when single ----------------
__global__ __launch_bounds__(192) void k_gather(const float* __restrict__ loc_orig,
                                                const int*   __restrict__ idx_agg,
                                                const float* __restrict__ agg_w,
                                                float*       __restrict__ out) {
    int p = blockIdx.x;
    int b = p / N0;
    float px = pix_coord(loc_orig[2*p],   (float)WW);
    float py = pix_coord(loc_orig[2*p+1], (float)HH);
    int x0 = min(max((int)floorf(px), 0), WW-1);
    int y0 = min(max((int)floorf(py), 0), HH-1);
    int x1 = min(x0 + 1, WW-1);
    int y1 = min(y0 + 1, HH-1);
    float wx = fminf((float)x1, px) - (float)x0;   // replicates reference border quirk
    float wy = fminf((float)y1, py) - (float)y0;
    float w00 = (1.0f-wx)*(1.0f-wy);
    float w10 = wx*(1.0f-wy);
    float w01 = (1.0f-wx)*wy;
    float w11 = wx*wy;
    int base = b*HW;
    const __half* r00 = g_cv + (size_t)(base + y0*WW + x0)*CC;
    const __half* r10 = g_cv + (size_t)(base + y0*WW + x1)*CC;
    const __half* r01 = g_cv + (size_t)(base + y1*WW + x0)*CC;
    const __half* r11 = g_cv + (size_t)(base + y1*WW + x1)*CC;
    int tok = idx_agg[p];
    int seg = b*NN + tok;
    float scale = agg_w[p] * __ldg(&g_wsum[seg]);   // w / (wsum + eps)
    int tc = __ldg(&g_tcnt[seg]);
    float* dst = out + (size_t)seg*CC;
    int c4 = threadIdx.x;
    float4 a  = h4_to_f4(__ldg((const uint2*)r00 + c4));
    float4 bq = h4_to_f4(__ldg((const uint2*)r10 + c4));
    float4 cq = h4_to_f4(__ldg((const uint2*)r01 + c4));
    float4 dq = h4_to_f4(__ldg((const uint2*)r11 + c4));
    float4 v;
    v.x = (w00*a.x + w10*bq.x + w01*cq.x + w11*dq.x) * scale;
    v.y = (w00*a.y + w10*bq.y + w01*cq.y + w11*dq.y) * scale;
    v.z = (w00*a.z + w10*bq.z + w01*cq.z + w11*dq.z) * scale;
    v.w = (w00*a.w + w10*bq.w + w01*cq.w + w11*dq.w) * scale;
    if (tc == 1)
        ((float4*)dst)[c4] = v;
    else
        red_add4(dst + 4*c4, v);
}

// ---------------- launch: fork output-zeroing onto a side stream ----------------
extern "C" void kernel_launch(void* const* d_in, const int* in_sizes, int n_in,
                              void* d_out, int out_size) {
    const float* x        = (const float*)d_in[0];
    const float* loc_orig = (const float*)d_in[2];
    const int*   idx_agg  = (const int*)  d_in[3];
    const float* agg_w    = (const float*)d_in[4];
    const float* conv_w   = (const float*)d_in[n_in-2];
    const float* conv_b   = (const float*)d_in[n_in-1];
    float* out = (float*)d_out;

    static cudaStream_t s1 = nullptr;
    static cudaEvent_t evCnt = nullptr, evOut = nullptr;
    if (!s1) {
        cudaStreamCreateWithFlags(&s1, cudaStreamNonBlocking);
        cudaEventCreateWithFlags(&evCnt, cudaEventDisableTiming);
        cudaEventCreateWithFlags(&evOut, cudaEventDisableTiming);
    }
    cudaStream_t s0 = 0;  // capture stream (legacy default joins capture)

    // setup chain on s0
    k_zero_meta<<<(BB*HW + 255)/256, 256, 0, s0>>>();
    k_count<<<(NPTS + 255)/256, 256, 0, s0>>>(loc_orig, idx_agg, agg_w);
    cudaEventRecord(evCnt, s0);

    // side stream: zero output rows (needs only counts; must finish before gather)
    cudaStreamWaitEvent(s1, evCnt, 0);
    k_zero_out<<<148*4, 192, 0, s1>>>(out);
    cudaEventRecord(evOut, s1);

    // main chain
    {
        int total = 9*CC + BB*HW + BB*NN;
        k_prep<<<(total + 255)/256, 256, 0, s0>>>(conv_w);
    }
    k_zero_raw<<<148*8, 192, 0, s0>>>();
    k_scatter<<<NPTS, 192, 0, s0>>>(x, loc_orig, idx_agg);
    {
        dim3 cgrid(WW/XSEG, BB*HH);          // 4 x 1024
        k_conv<<<cgrid, 192, 0, s0>>>(conv_b);
    }
    cudaStreamWaitEvent(s0, evOut, 0);
    k_gather<<<NPTS, 192, 0, s0>>>(loc_orig, idx_agg, agg_w, out);
}

// round 12
// speedup vs baseline: 1.0197x; 1.0197x over previous
#include <cuda_runtime.h>
#include <cuda_fp16.h>
#include <cstdint>

// Problem constants (fixed shapes from setup_inputs)
#define BB   16
#define NN   1536
#define CC   768
#define N0   3072
#define HH   64
#define WW   48
#define HW   (HH*WW)            // 3072
#define FM   (BB*HW*CC)         // 37,748,736 elements
#define NPTS (BB*N0)            // 49,152
#define EPSF 1e-6f
#define XSEG 24                 // conv columns per block (2 segments per row)

// Scratch (device globals: allocation-free, per harness rules)
__device__ __align__(16) __half g_raw [FM];      // normalized token2map map, fp16
__device__ __align__(16) __half g_cv  [FM];      // post-conv map,            fp16
__device__ __align__(16) float  g_rc  [BB*HW];   // 1/(cnt+eps), 0 for empty pixels
__device__ __align__(16) float  g_wsum[BB*NN];   // sum(agg_w) -> 1/(sum+eps)
__device__ __align__(16) float  g_wT  [9*CC];    // conv weights transposed [k][C]
__device__ int g_icnt[BB*HW];                    // per-pixel point count
__device__ int g_tcnt[BB*NN];                    // per-token point count

__device__ __forceinline__ void red_add4(float* p, float4 v) {
    asm volatile("red.global.add.v4.f32 [%0], {%1,%2,%3,%4};"
                 :: "l"(p), "f"(v.x), "f"(v.y), "f"(v.z), "f"(v.w) : "memory");
}
// single 8-byte vector fp16 reduction (one REDG op for 4 halfs)
__device__ __forceinline__ void red_addh4(unsigned* p, uint2 v) {
    asm volatile("red.global.add.noftz.v2.f16x2 [%0], {%1,%2};"
                 :: "l"(p), "r"(v.x), "r"(v.y) : "memory");
}

// pixel coords matching jnp: pos = 0.5*(clip(loc,-1,1)+1)*wh - 0.5, unfused to match rounding
__device__ __forceinline__ float pix_coord(float l, float wh) {
    l = fminf(fmaxf(l, -1.0f), 1.0f);
    float t = __fmul_rn(0.5f, __fadd_rn(l, 1.0f));
    return __fadd_rn(__fmul_rn(t, wh), -0.5f);
}

__device__ __forceinline__ float4 h4_to_f4(uint2 pk) {
    __half2 h0 = *(__half2*)&pk.x;
    __half2 h1 = *(__half2*)&pk.y;
    float2 f0 = __half22float2(h0);
    float2 f1 = __half22float2(h1);
    return make_float4(f0.x, f0.y, f1.x, f1.y);
}
__device__ __forceinline__ uint2 f4_to_h4(float4 v) {
    __half2 h0 = __float22half2_rn(make_float2(v.x, v.y));
    __half2 h1 = __float22half2_rn(make_float2(v.z, v.w));
    uint2 pk;
    pk.x = *(unsigned*)&h0;
    pk.y = *(unsigned*)&h1;
    return pk;
}

// ---------------- zero small metadata ----------------
__global__ void k_zero_meta() {
    int i = blockIdx.x * blockDim.x + threadIdx.x;
    if (i < BB*HW) g_icnt[i] = 0;
    if (i < BB*NN) { g_tcnt[i] = 0; g_wsum[i] = 0.0f; }
}

// ---------------- counts + weight sums ----------------
__global__ void k_count(const float* __restrict__ loc_orig,
                        const int*   __restrict__ idx_agg,
                        const float* __restrict__ agg_w) {
    int p = blockIdx.x * blockDim.x + threadIdx.x;
    if (p >= NPTS) return;
    int b = p / N0;
    float px = pix_coord(loc_orig[2*p],   (float)WW);
    float py = pix_coord(loc_orig[2*p+1], (float)HH);
    int ix = min(max((int)rintf(px), 0), WW-1);   // rintf = round-half-even = jnp.round
    int iy = min(max((int)rintf(py), 0), HH-1);
    atomicAdd(&g_icnt[b*HW + iy*WW + ix], 1);
    int seg = b*NN + idx_agg[p];
    atomicAdd(&g_tcnt[seg], 1);
    atomicAdd(&g_wsum[seg], agg_w[p]);
}

// ---------------- reciprocals + weight transpose ----------------
__global__ void k_prep(const float* __restrict__ conv_w) {
    int i = blockIdx.x * blockDim.x + threadIdx.x;
    if (i < 9*CC) {
        int c = i / 9, k = i % 9;           // conv_w layout [C][1][3][3]
        g_wT[k*CC + c] = conv_w[i];
    } else if (i < 9*CC + BB*HW) {
        int j = i - 9*CC;
        int n = g_icnt[j];
        g_rc[j] = (n > 0) ? 1.0f / ((float)n + EPSF) : 0.0f;
    } else if (i < 9*CC + BB*HW + BB*NN) {
        int j = i - 9*CC - BB*HW;
        g_wsum[j] = 1.0f / (g_wsum[j] + EPSF);
    }
}

// ---------------- zero fp16 raw rows with cnt>=2 (persistent, 4-row unroll) ----------------
__global__ __launch_bounds__(192) void k_zero_raw() {
    const int c4 = threadIdx.x;
    const uint2 z = make_uint2(0u, 0u);
    for (int base = blockIdx.x * 4; base < BB*HW; base += gridDim.x * 4) {
        int need[4];
        #pragma unroll
        for (int j = 0; j < 4; j++)
            need[j] = (base + j < BB*HW) && (__ldg(&g_icnt[base+j]) >= 2);
        #pragma unroll
        for (int j = 0; j < 4; j++)
            if (need[j]) ((uint2*)(g_raw + (size_t)(base+j)*CC))[c4] = z;
    }
}

// ---------------- zero out rows with tcnt!=1 (runs on side stream) ----------------
__global__ __launch_bounds__(192) void k_zero_out(float* __restrict__ out) {
    const int c4 = threadIdx.x;
    const float4 z = make_float4(0.f, 0.f, 0.f, 0.f);
    for (int base = blockIdx.x * 4; base < BB*NN; base += gridDim.x * 4) {
        int need[4];
        #pragma unroll
        for (int j = 0; j < 4; j++)
            need[j] = (base + j < BB*NN) && (__ldg(&g_tcnt[base+j]) != 1);
        #pragma unroll
        for (int j = 0; j < 4; j++)
            if (need[j]) ((float4*)(out + (size_t)(base+j)*CC))[c4] = z;
    }
}

// ---------------- feature scatter, pre-normalized, fp16 map; STG when single ----------------
__global__ __launch_bounds__(192) void k_scatter(const float* __restrict__ x,
                                                 const float* __restrict__ loc_orig,
                                                 const int*   __restrict__ idx_agg) {
    int p = blockIdx.x;
    int b = p / N0;
    float px = pix_coord(loc_orig[2*p],   (float)WW);
    float py = pix_coord(loc_orig[2*p+1], (float)HH);
    int ix = min(max((int)rintf(px), 0), WW-1);
    int iy = min(max((int)rintf(py), 0), HH-1);
    int pix = b*HW + iy*WW + ix;
    int tok = idx_agg[p];
    float rc = __ldg(&g_rc[pix]);            // 1/(cnt+eps)
    int cnt  = __ldg(&g_icnt[pix]);
    const float4* src = (const float4*)(x + ((size_t)b*NN + tok)*CC);
    __half* dst = g_raw + (size_t)pix*CC;
    int c4 = threadIdx.x;                    // 192 threads, C/4 = 192
    float4 v = __ldg(&src[c4]);
    v.x *= rc; v.y *= rc; v.z *= rc; v.w *= rc;
    uint2 pk = f4_to_h4(v);
    if (cnt == 1)
        ((uint2*)dst)[c4] = pk;
    else
        red_addh4((unsigned*)dst + 2*c4, pk);   // ONE vector REDG per thread
}

// ---------------- row-sliding depthwise 3x3 conv, fp16 in/out, software-pipelined ----------------
__global__ __launch_bounds__(192) void k_conv(const float* __restrict__ conv_b) {
    __shared__ float s_rc[3][WW];
    const int seg = blockIdx.x;              // column segment (WW/XSEG of them)
    const int by  = blockIdx.y;              // b*HH + y
    const int b   = by / HH;
    const int y   = by - b*HH;
    const int tid = threadIdx.x;
    const int x0  = seg * XSEG;

    // rc masks for rows y-1..y+1 (0 outside image / empty pixel)
    for (int i = tid; i < 3*WW; i += 192) {
        int r = i / WW, xx = i - (i / WW)*WW;
        int gy = y + r - 1;
        s_rc[r][xx] = (gy >= 0 && gy < HH) ? __ldg(&g_rc[b*HW + gy*WW + xx]) : 0.0f;
    }
    __syncthreads();

    const int c4 = tid;
    float4 w[9];
    #pragma unroll
    for (int k = 0; k < 9; k++)
        w[k] = *(const float4*)(g_wT + k*CC + 4*c4);
    const float4 bias = ((const float4*)conv_b)[c4];

    const float4 z = make_float4(0.f, 0.f, 0.f, 0.f);
    const size_t rowbase = (size_t)b*HW + (size_t)(y-1)*WW;

    // masked fp16 column load: row r (0..2), column x
    auto ldc = [&](int r, int x) -> float4 {
        if (x < 0 || x >= WW || s_rc[r][x] == 0.0f) return z;
        uint2 pk = __ldg(((const uint2*)(g_raw + (rowbase + (size_t)r*WW + x)*CC)) + c4);
        return h4_to_f4(pk);
    };

    float4 win[3][3];                        // [row][cpos]: 0 = x-1, 1 = x, 2 = x+1
    float4 nxt[3];
    #pragma unroll
    for (int r = 0; r < 3; r++) {
        win[r][0] = ldc(r, x0 - 1);
        win[r][1] = ldc(r, x0);
        nxt[r]    = ldc(r, x0 + 1);
    }

    for (int xi = 0; xi < XSEG; xi++) {
        int x = x0 + xi;
        #pragma unroll
        for (int r = 0; r < 3; r++) win[r][2] = nxt[r];
        // prefetch column x+2 (consumed next iteration -> latency hidden)
        float4 pf[3];
        #pragma unroll
        for (int r = 0; r < 3; r++) pf[r] = ldc(r, x + 2);
        // compute
        float4 acc = bias;
        #pragma unroll
        for (int r = 0; r < 3; r++) {
            #pragma unroll
            for (int cc = 0; cc < 3; cc++) {
                float4 v = win[r][cc];
                float4 wv = w[r*3 + cc];
                acc.x += v.x * wv.x;
                acc.y += v.y * wv.y;
                acc.z += v.z * wv.z;
                acc.w += v.w * wv.w;
            }
        }
        ((uint2*)(g_cv + ((size_t)b*HW + (size_t)y*WW + x)*CC))[c4] = f4_to_h4(acc);
        // shift window
        #pragma unroll
        for (int r = 0; r < 3; r++) {
            win[r][0] = win[r][1];
            win[r][1] = win[r][2];
            nxt[r]    = pf[r];
        }
    }
}

// ---------------- bilinear gather (fp16 map) + token aggregation; STG when single ----------------
__global__ __launch_bounds__(192) void k_gather(const float* __restrict__ loc_orig,
                                                const int*   __restrict__ idx_agg,
                                                const float* __restrict__ agg_w,
                                                float*       __restrict__ out) {
    int p = blockIdx.x;
    int b = p / N0;
    float px = pix_coord(loc_orig[2*p],   (float)WW);
    float py = pix_coord(loc_orig[2*p+1], (float)HH);
    int x0 = min(max((int)floorf(px), 0), WW-1);
    int y0 = min(max((int)floorf(py), 0), HH-1);
    int x1 = min(x0 + 1, WW-1);
    int y1 = min(y0 + 1, HH-1);
    float wx = fminf((float)x1, px) - (float)x0;   // replicates reference border quirk
    float wy = fminf((float)y1, py) - (float)y0;
    float w00 = (1.0f-wx)*(1.0f-wy);
    float w10 = wx*(1.0f-wy);
    float w01 = (1.0f-wx)*wy;
    float w11 = wx*wy;
    int base = b*HW;
    const __half* r00 = g_cv + (size_t)(base + y0*WW + x0)*CC;
    const __half* r10 = g_cv + (size_t)(base + y0*WW + x1)*CC;
    const __half* r01 = g_cv + (size_t)(base + y1*WW + x0)*CC;
    const __half* r11 = g_cv + (size_t)(base + y1*WW + x1)*CC;
    int tok = idx_agg[p];
    int seg = b*NN + tok;
    float scale = agg_w[p] * __ldg(&g_wsum[seg]);   // w / (wsum + eps)
    int tc = __ldg(&g_tcnt[seg]);
    float* dst = out + (size_t)seg*CC;
    int c4 = threadIdx.x;
    float4 a  = h4_to_f4(__ldg((const uint2*)r00 + c4));
    float4 bq = h4_to_f4(__ldg((const uint2*)r10 + c4));
    float4 cq = h4_to_f4(__ldg((const uint2*)r01 + c4));
    float4 dq = h4_to_f4(__ldg((const uint2*)r11 + c4));
    float4 v;
    v.x = (w00*a.x + w10*bq.x + w01*cq.x + w11*dq.x) * scale;
    v.y = (w00*a.y + w10*bq.y + w01*cq.y + w11*dq.y) * scale;
    v.z = (w00*a.z + w10*bq.z + w01*cq.z + w11*dq.z) * scale;
    v.w = (w00*a.w + w10*bq.w + w01*cq.w + w11*dq.w) * scale;
    if (tc == 1)
        ((float4*)dst)[c4] = v;
    else
        red_add4(dst + 4*c4, v);
}

// ---------------- launch: fork output-zeroing onto a side stream ----------------
extern "C" void kernel_launch(void* const* d_in, const int* in_sizes, int n_in,
                              void* d_out, int out_size) {
    const float* x        = (const float*)d_in[0];
    const float* loc_orig = (const float*)d_in[2];
    const int*   idx_agg  = (const int*)  d_in[3];
    const float* agg_w    = (const float*)d_in[4];
    const float* conv_w   = (const float*)d_in[n_in-2];
    const float* conv_b   = (const float*)d_in[n_in-1];
    float* out = (float*)d_out;

    static cudaStream_t s1 = nullptr;
    static cudaEvent_t evCnt = nullptr, evOut = nullptr;
    if (!s1) {
        cudaStreamCreateWithFlags(&s1, cudaStreamNonBlocking);
        cudaEventCreateWithFlags(&evCnt, cudaEventDisableTiming);
        cudaEventCreateWithFlags(&evOut, cudaEventDisableTiming);
    }
    cudaStream_t s0 = 0;  // capture stream (legacy default joins capture)

    // setup chain on s0
    k_zero_meta<<<(BB*HW + 255)/256, 256, 0, s0>>>();
    k_count<<<(NPTS + 255)/256, 256, 0, s0>>>(loc_orig, idx_agg, agg_w);
    cudaEventRecord(evCnt, s0);

    // side stream: zero output rows (needs only counts; must finish before gather)
    cudaStreamWaitEvent(s1, evCnt, 0);
    k_zero_out<<<148*4, 192, 0, s1>>>(out);
    cudaEventRecord(evOut, s1);

    // main chain
    {
        int total = 9*CC + BB*HW + BB*NN;
        k_prep<<<(total + 255)/256, 256, 0, s0>>>(conv_w);
    }
    k_zero_raw<<<148*8, 192, 0, s0>>>();
    k_scatter<<<NPTS, 192, 0, s0>>>(x, loc_orig, idx_agg);
    {
        dim3 cgrid(WW/XSEG, BB*HH);          // 2 x 1024
        k_conv<<<cgrid, 192, 0, s0>>>(conv_b);
    }
    cudaStreamWaitEvent(s0, evOut, 0);
    k_gather<<<NPTS, 192, 0, s0>>>(loc_orig, idx_agg, agg_w, out);
}

// round 13
// speedup vs baseline: 1.1798x; 1.1570x over previous
#include <cuda_runtime.h>
#include <cuda_fp16.h>
#include <cstdint>

// Problem constants (fixed shapes from setup_inputs)
#define BB   16
#define NN   1536
#define CC   768
#define N0   3072
#define HH   64
#define WW   48
#define HW   (HH*WW)            // 3072
#define FM   (BB*HW*CC)         // 37,748,736 elements
#define NPTS (BB*N0)            // 49,152
#define EPSF 1e-6f
#define XSEG 24                 // conv columns per block (2 segments per row)
#define HALFB (BB/2)            // batches per pipeline chunk

// Scratch (device globals: allocation-free, per harness rules)
__device__ __align__(16) float  g_raw [FM];      // normalized token2map map, fp32
__device__ __align__(16) __half g_cv  [FM];      // post-conv map,            fp16
__device__ __align__(16) float  g_rc  [BB*HW];   // 1/(cnt+eps), 0 for empty pixels
__device__ __align__(16) float  g_wsum[BB*NN];   // sum(agg_w) -> 1/(sum+eps)
__device__ __align__(16) float  g_wT  [9*CC];    // conv weights transposed [k][C]
__device__ int g_icnt[BB*HW];                    // per-pixel point count
__device__ int g_tcnt[BB*NN];                    // per-token point count

__device__ __forceinline__ void red_add4(float* p, float4 v) {
    asm volatile("red.global.add.v4.f32 [%0], {%1,%2,%3,%4};"
                 :: "l"(p), "f"(v.x), "f"(v.y), "f"(v.z), "f"(v.w) : "memory");
}

// pixel coords matching jnp: pos = 0.5*(clip(loc,-1,1)+1)*wh - 0.5, unfused to match rounding
__device__ __forceinline__ float pix_coord(float l, float wh) {
    l = fminf(fmaxf(l, -1.0f), 1.0f);
    float t = __fmul_rn(0.5f, __fadd_rn(l, 1.0f));
    return __fadd_rn(__fmul_rn(t, wh), -0.5f);
}

__device__ __forceinline__ float4 h4_to_f4(uint2 pk) {
    __half2 h0 = *(__half2*)&pk.x;
    __half2 h1 = *(__half2*)&pk.y;
    float2 f0 = __half22float2(h0);
    float2 f1 = __half22float2(h1);
    return make_float4(f0.x, f0.y, f1.x, f1.y);
}
__device__ __forceinline__ uint2 f4_to_h4(float4 v) {
    __half2 h0 = __float22half2_rn(make_float2(v.x, v.y));
    __half2 h1 = __float22half2_rn(make_float2(v.z, v.w));
    uint2 pk;
    pk.x = *(unsigned*)&h0;
    pk.y = *(unsigned*)&h1;
    return pk;
}

// ---------------- zero small metadata ----------------
__global__ void k_zero_meta() {
    int i = blockIdx.x * blockDim.x + threadIdx.x;
    if (i < BB*HW) g_icnt[i] = 0;
    if (i < BB*NN) { g_tcnt[i] = 0; g_wsum[i] = 0.0f; }
}

// ---------------- counts + weight sums ----------------
__global__ void k_count(const float* __restrict__ loc_orig,
                        const int*   __restrict__ idx_agg,
                        const float* __restrict__ agg_w) {
    int p = blockIdx.x * blockDim.x + threadIdx.x;
    if (p >= NPTS) return;
    int b = p / N0;
    float px = pix_coord(loc_orig[2*p],   (float)WW);
    float py = pix_coord(loc_orig[2*p+1], (float)HH);
    int ix = min(max((int)rintf(px), 0), WW-1);   // rintf = round-half-even = jnp.round
    int iy = min(max((int)rintf(py), 0), HH-1);
    atomicAdd(&g_icnt[b*HW + iy*WW + ix], 1);
    int seg = b*NN + idx_agg[p];
    atomicAdd(&g_tcnt[seg], 1);
    atomicAdd(&g_wsum[seg], agg_w[p]);
}

// ---------------- reciprocals + weight transpose ----------------
__global__ void k_prep(const float* __restrict__ conv_w) {
    int i = blockIdx.x * blockDim.x + threadIdx.x;
    if (i < 9*CC) {
        int c = i / 9, k = i % 9;           // conv_w layout [C][1][3][3]
        g_wT[k*CC + c] = conv_w[i];
    } else if (i < 9*CC + BB*HW) {
        int j = i - 9*CC;
        int n = g_icnt[j];
        g_rc[j] = (n > 0) ? 1.0f / ((float)n + EPSF) : 0.0f;
    } else if (i < 9*CC + BB*HW + BB*NN) {
        int j = i - 9*CC - BB*HW;
        g_wsum[j] = 1.0f / (g_wsum[j] + EPSF);
    }
}

// ---------------- zero fp32 raw rows with cnt>=2 (persistent, 4-row unroll) ----------------
__global__ __launch_bounds__(192) void k_zero_raw() {
    const int c4 = threadIdx.x;
    const float4 z = make_float4(0.f, 0.f, 0.f, 0.f);
    for (int base = blockIdx.x * 4; base < BB*HW; base += gridDim.x * 4) {
        int need[4];
        #pragma unroll
        for (int j = 0; j < 4; j++)
            need[j] = (base + j < BB*HW) && (__ldg(&g_icnt[base+j]) >= 2);
        #pragma unroll
        for (int j = 0; j < 4; j++)
            if (need[j]) ((float4*)(g_raw + (size_t)(base+j)*CC))[c4] = z;
    }
}

// ---------------- zero out rows with tcnt!=1 (runs on side stream) ----------------
__global__ __launch_bounds__(192) void k_zero_out(float* __restrict__ out) {
    const int c4 = threadIdx.x;
    const float4 z = make_float4(0.f, 0.f, 0.f, 0.f);
    for (int base = blockIdx.x * 4; base < BB*NN; base += gridDim.x * 4) {
        int need[4];
        #pragma unroll
        for (int j = 0; j < 4; j++)
            need[j] = (base + j < BB*NN) && (__ldg(&g_tcnt[base+j]) != 1);
        #pragma unroll
        for (int j = 0; j < 4; j++)
            if (need[j]) ((float4*)(out + (size_t)(base+j)*CC))[c4] = z;
    }
}

// ---------------- feature scatter (batch chunk), pre-normalized; STG when single ----------------
__global__ __launch_bounds__(192) void k_scatter(const float* __restrict__ x,
                                                 const float* __restrict__ loc_orig,
                                                 const int*   __restrict__ idx_agg,
                                                 int pbase) {
    int p = pbase + blockIdx.x;
    int b = p / N0;
    float px = pix_coord(loc_orig[2*p],   (float)WW);
    float py = pix_coord(loc_orig[2*p+1], (float)HH);
    int ix = min(max((int)rintf(px), 0), WW-1);
    int iy = min(max((int)rintf(py), 0), HH-1);
    int pix = b*HW + iy*WW + ix;
    int tok = idx_agg[p];
    float rc = __ldg(&g_rc[pix]);            // 1/(cnt+eps)
    int cnt  = __ldg(&g_icnt[pix]);
    const float4* src = (const float4*)(x + ((size_t)b*NN + tok)*CC);
    float* dst = g_raw + (size_t)pix*CC;
    int c4 = threadIdx.x;                    // 192 threads, C/4 = 192
    float4 v = __ldg(&src[c4]);
    v.x *= rc; v.y *= rc; v.z *= rc; v.w *= rc;
    if (cnt == 1)
        ((float4*)dst)[c4] = v;
    else
        red_add4(dst + 4*c4, v);
}

// ---------------- row-sliding depthwise 3x3 conv (batch chunk), fp16 out ----------------
__global__ __launch_bounds__(192) void k_conv(const float* __restrict__ conv_b, int bbase) {
    __shared__ float s_rc[3][WW];
    const int seg = blockIdx.x;              // 0 or 1: column segment
    const int by  = blockIdx.y;              // local (b-bbase)*HH + y
    const int b   = bbase + by / HH;
    const int y   = by % HH;
    const int tid = threadIdx.x;
    const int x0  = seg * XSEG;

    // rc masks for rows y-1..y+1 (0 outside image / empty pixel)
    for (int i = tid; i < 3*WW; i += 192) {
        int r = i / WW, xx = i - (i / WW)*WW;
        int gy = y + r - 1;
        s_rc[r][xx] = (gy >= 0 && gy < HH) ? __ldg(&g_rc[b*HW + gy*WW + xx]) : 0.0f;
    }
    __syncthreads();

    const int c4 = tid;
    float4 w[9];
    #pragma unroll
    for (int k = 0; k < 9; k++)
        w[k] = *(const float4*)(g_wT + k*CC + 4*c4);
    const float4 bias = ((const float4*)conv_b)[c4];

    const float4 z = make_float4(0.f, 0.f, 0.f, 0.f);
    const size_t rowbase = (size_t)b*HW + (size_t)(y-1)*WW;

    auto ldc = [&](int r, int x) -> float4 {
        if (x < 0 || x >= WW || s_rc[r][x] == 0.0f) return z;
        return *(const float4*)(g_raw + (rowbase + (size_t)r*WW + x)*CC + 4*c4);
    };

    float4 win[3][3];                        // [row][cpos]: 0 = x-1, 1 = x, 2 = x+1
    float4 nxt[3];
    #pragma unroll
    for (int r = 0; r < 3; r++) {
        win[r][0] = ldc(r, x0 - 1);
        win[r][1] = ldc(r, x0);
        nxt[r]    = ldc(r, x0 + 1);
    }

    for (int xi = 0; xi < XSEG; xi++) {
        int x = x0 + xi;
        #pragma unroll
        for (int r = 0; r < 3; r++) win[r][2] = nxt[r];
        // prefetch column x+2 (consumed next iteration -> latency hidden)
        float4 pf[3];
        #pragma unroll
        for (int r = 0; r < 3; r++) pf[r] = ldc(r, x + 2);
        // compute
        float4 acc = bias;
        #pragma unroll
        for (int r = 0; r < 3; r++) {
            #pragma unroll
            for (int cc = 0; cc < 3; cc++) {
                float4 v = win[r][cc];
                float4 wv = w[r*3 + cc];
                acc.x += v.x * wv.x;
                acc.y += v.y * wv.y;
                acc.z += v.z * wv.z;
                acc.w += v.w * wv.w;
            }
        }
        ((uint2*)(g_cv + ((size_t)b*HW + (size_t)y*WW + x)*CC))[c4] = f4_to_h4(acc);
        // shift window
        #pragma unroll
        for (int r = 0; r < 3; r++) {
            win[r][0] = win[r][1];
            win[r][1] = win[r][2];
            nxt[r]    = pf[r];
        }
    }
}

// ---------------- bilinear gather (fp16 map) + token aggregation; STG when single ----------------
__global__ __launch_bounds__(192) void k_gather(const float* __restrict__ loc_orig,
                                                const int*   __restrict__ idx_agg,
                                                const float* __restrict__ agg_w,
                                                float*       __restrict__ out) {
    int p = blockIdx.x;
    int b = p / N0;
    float px = pix_coord(loc_orig[2*p],   (float)WW);
    float py = pix_coord(loc_orig[2*p+1], (float)HH);
    int x0 = min(max((int)floorf(px), 0), WW-1);
    int y0 = min(max((int)floorf(py), 0), HH-1);
    int x1 = min(x0 + 1, WW-1);
    int y1 = min(y0 + 1, HH-1);
    float wx = fminf((float)x1, px) - (float)x0;   // replicates reference border quirk
    float wy = fminf((float)y1, py) - (float)y0;
    float w00 = (1.0f-wx)*(1.0f-wy);
    float w10 = wx*(1.0f-wy);
    float w01 = (1.0f-wx)*wy;
    float w11 = wx*wy;
    int base = b*HW;
    const __half* r00 = g_cv + (size_t)(base + y0*WW + x0)*CC;
    const __half* r10 = g_cv + (size_t)(base + y0*WW + x1)*CC;
    const __half* r01 = g_cv + (size_t)(base + y1*WW + x0)*CC;
    const __half* r11 = g_cv + (size_t)(base + y1*WW + x1)*CC;
    int tok = idx_agg[p];
    int seg = b*NN + tok;
    float scale = agg_w[p] * __ldg(&g_wsum[seg]);   // w / (wsum + eps)
    int tc = __ldg(&g_tcnt[seg]);
    float* dst = out + (size_t)seg*CC;
    int c4 = threadIdx.x;
    float4 a  = h4_to_f4(__ldg((const uint2*)r00 + c4));
    float4 bq = h4_to_f4(__ldg((const uint2*)r10 + c4));
    float4 cq = h4_to_f4(__ldg((const uint2*)r01 + c4));
    float4 dq = h4_to_f4(__ldg((const uint2*)r11 + c4));
    float4 v;
    v.x = (w00*a.x + w10*bq.x + w01*cq.x + w11*dq.x) * scale;
    v.y = (w00*a.y + w10*bq.y + w01*cq.y + w11*dq.y) * scale;
    v.z = (w00*a.z + w10*bq.z + w01*cq.z + w11*dq.z) * scale;
    v.w = (w00*a.w + w10*bq.w + w01*cq.w + w11*dq.w) * scale;
    if (tc == 1)
        ((float4*)dst)[c4] = v;
    else
        red_add4(dst + 4*c4, v);
}

// ---------------- launch: chunked scatter->conv pipeline across two streams ----------------
extern "C" void kernel_launch(void* const* d_in, const int* in_sizes, int n_in,
                              void* d_out, int out_size) {
    const float* x        = (const float*)d_in[0];
    const float* loc_orig = (const float*)d_in[2];
    const int*   idx_agg  = (const int*)  d_in[3];
    const float* agg_w    = (const float*)d_in[4];
    const float* conv_w   = (const float*)d_in[n_in-2];
    const float* conv_b   = (const float*)d_in[n_in-1];
    float* out = (float*)d_out;

    static cudaStream_t s1 = nullptr, s2 = nullptr;
    static cudaEvent_t evCnt = nullptr, evOut = nullptr, evS0 = nullptr, evC1 = nullptr;
    if (!s1) {
        cudaStreamCreateWithFlags(&s1, cudaStreamNonBlocking);
        cudaStreamCreateWithFlags(&s2, cudaStreamNonBlocking);
        cudaEventCreateWithFlags(&evCnt, cudaEventDisableTiming);
        cudaEventCreateWithFlags(&evOut, cudaEventDisableTiming);
        cudaEventCreateWithFlags(&evS0,  cudaEventDisableTiming);
        cudaEventCreateWithFlags(&evC1,  cudaEventDisableTiming);
    }
    cudaStream_t s0 = 0;  // capture stream (legacy default joins capture)

    // setup chain on s0
    k_zero_meta<<<(BB*HW + 255)/256, 256, 0, s0>>>();
    k_count<<<(NPTS + 255)/256, 256, 0, s0>>>(loc_orig, idx_agg, agg_w);
    cudaEventRecord(evCnt, s0);

    // side stream: zero output rows (needs only counts; must finish before gather)
    cudaStreamWaitEvent(s1, evCnt, 0);
    k_zero_out<<<148*4, 192, 0, s1>>>(out);
    cudaEventRecord(evOut, s1);

    // main chain: prep + raw zeroing
    {
        int total = 9*CC + BB*HW + BB*NN;
        k_prep<<<(total + 255)/256, 256, 0, s0>>>(conv_w);
    }
    k_zero_raw<<<148*8, 192, 0, s0>>>();

    // chunk 0 on s0: scatter then conv
    k_scatter<<<HALFB*N0, 192, 0, s0>>>(x, loc_orig, idx_agg, 0);
    cudaEventRecord(evS0, s0);
    {
        dim3 cgrid(WW/XSEG, HALFB*HH);       // 2 x 512
        k_conv<<<cgrid, 192, 0, s0>>>(conv_b, 0);
    }

    // chunk 1 on s2: scatter (after chunk0 scatter retires) then conv — overlaps conv0
    cudaStreamWaitEvent(s2, evS0, 0);
    k_scatter<<<HALFB*N0, 192, 0, s2>>>(x, loc_orig, idx_agg, HALFB*N0);
    {
        dim3 cgrid(WW/XSEG, HALFB*HH);
        k_conv<<<cgrid, 192, 0, s2>>>(conv_b, HALFB);
    }
    cudaEventRecord(evC1, s2);

    // gather after both convs + output zeroing
    cudaStreamWaitEvent(s0, evC1, 0);
    cudaStreamWaitEvent(s0, evOut, 0);
    k_gather<<<NPTS, 192, 0, s0>>>(loc_orig, idx_agg, agg_w, out);
}